// round 1
// baseline (speedup 1.0000x reference)
#include <cuda_runtime.h>
#include <math.h>

#define N_ROWS 500000
#define D 128
#define H 128
#define GDIM 64
#define M 256
#define TILE_R 128
#define CHUNK_H 32
#define BSTRIDE 129   // 128+1: consecutive rows land in consecutive banks

// Scratch (no allocations allowed)
__device__ float g_A[N_ROWS];
__device__ float g_max;
__device__ float g_sumexp;
__device__ float g_wsum[D];

__device__ __forceinline__ void atomicMaxFloat(float* addr, float val) {
    int* ai = (int*)addr;
    int old = *ai;
    while (__int_as_float(old) < val) {
        int assumed = old;
        old = atomicCAS(ai, assumed, __float_as_int(val));
        if (old == assumed) break;
    }
}

__global__ void k_init() {
    int t = threadIdx.x;
    if (t < D) g_wsum[t] = 0.f;
    if (t == 0) { g_max = -INFINITY; g_sumexp = 0.f; }
}

// ---------------------------------------------------------------------------
// K1: A_raw[n] = sum_h Ww[h] * tanh(bag[n]·Wv[h] + bv[h]) * sigmoid(bag[n]·Wu[h] + bu[h]) + bw
// Block: 256 threads, 128-row tile. h processed in chunks of 32 (4 h per warp).
// Each thread: 4 rows (lane, lane+32, lane+64, lane+96) x 4 h, V and U accums.
// ---------------------------------------------------------------------------
__global__ void k_scores(const float* __restrict__ bag,
                         const float* __restrict__ Wv, const float* __restrict__ bv,
                         const float* __restrict__ Wu, const float* __restrict__ bu,
                         const float* __restrict__ Ww, const float* __restrict__ bwp)
{
    extern __shared__ float smem[];
    float* sBag = smem;                          // TILE_R * BSTRIDE
    float* sWv  = sBag + TILE_R * BSTRIDE;       // CHUNK_H * D
    float* sWu  = sWv + CHUNK_H * D;             // CHUNK_H * D
    float* sA   = sWu + CHUNK_H * D;             // TILE_R

    const int tid  = threadIdx.x;
    const int lane = tid & 31;
    const int wid  = tid >> 5;
    const int row0 = blockIdx.x * TILE_R;

    // Load bag tile (float4 global loads, scalar smem stores due to 129 stride)
    for (int idx = tid; idx < TILE_R * (D / 4); idx += blockDim.x) {
        int r  = idx >> 5;       // 32 float4 per row
        int c4 = idx & 31;
        int grow = row0 + r;
        float4 v = make_float4(0.f, 0.f, 0.f, 0.f);
        if (grow < N_ROWS) v = ((const float4*)bag)[grow * (D / 4) + c4];
        float* dst = sBag + r * BSTRIDE + c4 * 4;
        dst[0] = v.x; dst[1] = v.y; dst[2] = v.z; dst[3] = v.w;
    }
    if (tid < TILE_R) sA[tid] = 0.f;

    const float bw0 = bwp[0];

    for (int ch = 0; ch < H; ch += CHUNK_H) {
        __syncthreads();
        // Load weight chunk (both Wv, Wu rows [ch, ch+32))
        for (int idx = tid; idx < CHUNK_H * (D / 4); idx += blockDim.x) {
            int hr = idx >> 5;
            int c4 = idx & 31;
            ((float4*)sWv)[hr * (D / 4) + c4] = ((const float4*)Wv)[(ch + hr) * (D / 4) + c4];
            ((float4*)sWu)[hr * (D / 4) + c4] = ((const float4*)Wu)[(ch + hr) * (D / 4) + c4];
        }
        __syncthreads();

        const int hbase = wid * 4; // this warp's 4 h within the chunk
        float accV[4][4] = {{0.f}}, accU[4][4] = {{0.f}};

        #pragma unroll 4
        for (int d = 0; d < D; d++) {
            float bvals[4];
            #pragma unroll
            for (int i = 0; i < 4; i++) bvals[i] = sBag[(lane + 32 * i) * BSTRIDE + d];
            float wv[4], wu[4];
            #pragma unroll
            for (int j = 0; j < 4; j++) {
                wv[j] = sWv[(hbase + j) * D + d];   // warp-broadcast
                wu[j] = sWu[(hbase + j) * D + d];
            }
            #pragma unroll
            for (int i = 0; i < 4; i++)
                #pragma unroll
                for (int j = 0; j < 4; j++) {
                    accV[i][j] += bvals[i] * wv[j];
                    accU[i][j] += bvals[i] * wu[j];
                }
        }

        float wwj[4], bvj[4], buj[4];
        #pragma unroll
        for (int j = 0; j < 4; j++) {
            int h = ch + hbase + j;
            wwj[j] = Ww[h]; bvj[j] = bv[h]; buj[j] = bu[h];
        }
        #pragma unroll
        for (int i = 0; i < 4; i++) {
            float pa = 0.f;
            #pragma unroll
            for (int j = 0; j < 4; j++) {
                float Vv = tanhf(accV[i][j] + bvj[j]);
                float Uu = 1.f / (1.f + expf(-(accU[i][j] + buj[j])));
                pa += wwj[j] * Vv * Uu;
            }
            atomicAdd(&sA[lane + 32 * i], pa);
        }
    }
    __syncthreads();

    float myA = -INFINITY;
    if (tid < TILE_R) {
        int grow = row0 + tid;
        float a = sA[tid] + bw0;
        if (grow < N_ROWS) { g_A[grow] = a; myA = a; }
    }
    // block max -> global
    float m = myA;
    #pragma unroll
    for (int o = 16; o; o >>= 1) m = fmaxf(m, __shfl_xor_sync(0xffffffffu, m, o));
    __syncthreads();                 // smem reuse safe
    if (lane == 0) sWv[wid] = m;
    __syncthreads();
    if (tid == 0) {
        float mm = -INFINITY;
        for (int w = 0; w < 8; w++) mm = fmaxf(mm, sWv[w]);
        atomicMaxFloat(&g_max, mm);
    }
}

// ---------------------------------------------------------------------------
// K2: S = sum exp(A - max);  wsum[d] = sum_n exp(A[n]-max) * bag[n,d]
// warp-per-row, lane covers 4 contiguous d (float4).
// ---------------------------------------------------------------------------
__global__ void k_sumweighted(const float* __restrict__ bag)
{
    __shared__ float sVec[D];
    __shared__ float sSum;
    const int tid = threadIdx.x, lane = tid & 31, wid = tid >> 5;
    if (tid < D) sVec[tid] = 0.f;
    if (tid == 0) sSum = 0.f;
    __syncthreads();

    const float gmax = g_max;
    float part[4] = {0.f, 0.f, 0.f, 0.f};
    float esum = 0.f;
    const int warpsTotal = gridDim.x * (blockDim.x >> 5);
    int row = blockIdx.x * (blockDim.x >> 5) + wid;
    for (; row < N_ROWS; row += warpsTotal) {
        float e = expf(g_A[row] - gmax);          // broadcast load
        float4 v = ((const float4*)bag)[row * (D / 4) + lane];
        part[0] += e * v.x; part[1] += e * v.y;
        part[2] += e * v.z; part[3] += e * v.w;
        esum += e;
    }
    #pragma unroll
    for (int i = 0; i < 4; i++) atomicAdd(&sVec[lane * 4 + i], part[i]);
    if (lane == 0) atomicAdd(&sSum, esum);
    __syncthreads();
    if (tid < D) atomicAdd(&g_wsum[tid], sVec[tid]);
    if (tid == D) atomicAdd(&g_sumexp, sSum);
}

// K3: alpha
__global__ void k_alpha(float* __restrict__ out)
{
    int i = blockIdx.x * blockDim.x + threadIdx.x;
    if (i < N_ROWS) {
        float invS = 1.f / g_sumexp;
        out[1 + i] = expf(g_A[i] - g_max) * invS;
    }
}

// K4: bag_emb = wsum/S; fused = [bag_emb, global_feat]; MLP -> score
__global__ void k_head(const float* __restrict__ gf,
                       const float* __restrict__ W1, const float* __restrict__ b1,
                       const float* __restrict__ W2, const float* __restrict__ b2,
                       float* __restrict__ out)
{
    __shared__ float fused[D + GDIM];
    __shared__ float hred[M];
    const int tid = threadIdx.x;
    const float invS = 1.f / g_sumexp;
    if (tid < D) fused[tid] = g_wsum[tid] * invS;
    else if (tid < D + GDIM) fused[tid] = gf[tid - D];
    __syncthreads();

    float acc = b1[tid];
    #pragma unroll 8
    for (int j = 0; j < D + GDIM; j++) acc += W1[tid * (D + GDIM) + j] * fused[j];
    float h = acc > 0.f ? acc : 0.01f * acc;     // leaky_relu(0.01)
    hred[tid] = h * W2[tid];
    __syncthreads();
    for (int s = M / 2; s; s >>= 1) {
        if (tid < s) hred[tid] += hred[tid + s];
        __syncthreads();
    }
    if (tid == 0) out[0] = hred[0] + b2[0];
}

extern "C" void kernel_launch(void* const* d_in, const int* in_sizes, int n_in,
                              void* d_out, int out_size)
{
    const float* bag = (const float*)d_in[0];
    const float* gf  = (const float*)d_in[1];
    const float* Wv  = (const float*)d_in[2];
    const float* bv  = (const float*)d_in[3];
    const float* Wu  = (const float*)d_in[4];
    const float* bu  = (const float*)d_in[5];
    const float* Ww  = (const float*)d_in[6];
    const float* bw  = (const float*)d_in[7];
    const float* W1  = (const float*)d_in[8];
    const float* b1  = (const float*)d_in[9];
    const float* W2  = (const float*)d_in[10];
    const float* b2  = (const float*)d_in[11];
    float* out = (float*)d_out;

    const size_t smem = (size_t)(TILE_R * BSTRIDE + 2 * CHUNK_H * D + TILE_R) * sizeof(float);
    cudaFuncSetAttribute(k_scores, cudaFuncAttributeMaxDynamicSharedMemorySize, (int)smem);

    k_init<<<1, 256>>>();
    const int nblk = (N_ROWS + TILE_R - 1) / TILE_R;
    k_scores<<<nblk, 256, smem>>>(bag, Wv, bv, Wu, bu, Ww, bw);
    k_sumweighted<<<1024, 256>>>(bag);
    k_alpha<<<(N_ROWS + 255) / 256, 256>>>(out);
    k_head<<<1, 256>>>(gf, W1, b1, W2, b2, out);
}

// round 3
// speedup vs baseline: 3.5027x; 3.5027x over previous
#include <cuda_runtime.h>
#include <math.h>
#include <stdint.h>

#define N_ROWS 500000
#define D 128
#define H 128
#define GDIM 64
#define M 256
#define TILE_R 64
#define NTILES ((N_ROWS + TILE_R - 1) / TILE_R)   // 7813
#define GRID_SCORES 148

#define A_ROW_F 132                   // 128 floats + 4 pad (conflict-free frag loads)
#define A_ROW_B (A_ROW_F * 4)         // 528 B (16B-aligned)
#define A_BUF_B (TILE_R * A_ROW_B)    // 33792 B
#define OFF_A0 0
#define OFF_A1 A_BUF_B
#define OFF_B  (2 * A_BUF_B)          // 67584
#define B_MAT_B 65536                 // per-matrix packed tf32: [ks16][n128][c4] float2
#define OFF_SE   (OFF_B + 2 * B_MAT_B)   // 198656
#define OFF_SACC (OFF_SE + 256)          // 198912
#define SMEM_TOTAL (OFF_SACC + 256)      // 199168

// -------- scratch --------
__device__ float g_E[N_ROWS];
__device__ float g_sumexp;
__device__ float g_wsum[D];

__device__ __forceinline__ uint32_t smem_u32(const void* p) {
    uint32_t a;
    asm("{ .reg .u64 t; cvta.to.shared.u64 t, %1; cvt.u32.u64 %0, t; }" : "=r"(a) : "l"(p));
    return a;
}
__device__ __forceinline__ uint32_t f2tf32(float f) {
    uint32_t r;
    asm("cvt.rna.tf32.f32 %0, %1;" : "=r"(r) : "f"(f));
    return r;
}
__device__ __forceinline__ void mma_tf32(float d[4], const uint32_t a[4], uint2 b) {
    asm volatile(
        "mma.sync.aligned.m16n8k8.row.col.f32.tf32.tf32.f32 "
        "{%0,%1,%2,%3}, {%4,%5,%6,%7}, {%8,%9}, {%0,%1,%2,%3};"
        : "+f"(d[0]), "+f"(d[1]), "+f"(d[2]), "+f"(d[3])
        : "r"(a[0]), "r"(a[1]), "r"(a[2]), "r"(a[3]), "r"(b.x), "r"(b.y));
}
__device__ __forceinline__ float tanh_fast(float x) {
    float r;
    asm("tanh.approx.f32 %0, %1;" : "=f"(r) : "f"(x));
    return r;
}

__device__ __forceinline__ void cp_tile(uint32_t sdst, const float* __restrict__ bag,
                                        int tile, int tid) {
    const int row0 = tile * TILE_R;
    #pragma unroll
    for (int i = 0; i < 8; i++) {
        int chunk = tid + i * 256;
        int row = chunk >> 5, off = chunk & 31;
        int grow = row0 + row;
        int ok = grow < N_ROWS;
        const float* src = bag + (size_t)(ok ? grow : 0) * 128 + off * 4;
        uint32_t dst = sdst + row * A_ROW_B + off * 16;
        int sz = ok ? 16 : 0;
        asm volatile("cp.async.ca.shared.global [%0], [%1], 16, %2;"
                     :: "r"(dst), "l"(src), "r"(sz) : "memory");
    }
}

__global__ void k_init() {
    int t = threadIdx.x;
    if (t < D) g_wsum[t] = 0.f;
    if (t == 0) g_sumexp = 0.f;
}

// ---------------------------------------------------------------------------
// Persistent: tf32 mma.sync GEMMs (V,U) + gated epilogue + fused exp/wsum
// ---------------------------------------------------------------------------
__global__ void __launch_bounds__(256, 1)
k_scores(const float* __restrict__ bag,
         const float* __restrict__ Wv, const float* __restrict__ bv,
         const float* __restrict__ Wu, const float* __restrict__ bu,
         const float* __restrict__ Ww, const float* __restrict__ bwp)
{
    extern __shared__ __align__(128) char smem[];
    const uint32_t sbase = smem_u32(smem);
    const int tid = threadIdx.x, lane = tid & 31, wid = tid >> 5;
    float* sE   = (float*)(smem + OFF_SE);
    float* sAcc = (float*)(smem + OFF_SACC);

    // ---- repack weights -> tf32 packed [mat][ks][n][c] float2{W[n][ks8+c], W[n][ks8+c+4]}
    for (int idx = tid; idx < 2 * 128 * 16; idx += 256) {
        int mat = idx >> 11, rem = idx & 2047, n = rem >> 4, ks = rem & 15;
        const float* wr = (mat ? Wu : Wv) + n * 128 + ks * 8;
        float4 lo = *(const float4*)(wr);
        float4 hi = *(const float4*)(wr + 4);
        uint4* dst = (uint4*)(smem + OFF_B + mat * B_MAT_B + ks * 4096 + n * 32);
        dst[0] = make_uint4(f2tf32(lo.x), f2tf32(hi.x), f2tf32(lo.y), f2tf32(hi.y));
        dst[1] = make_uint4(f2tf32(lo.z), f2tf32(hi.z), f2tf32(lo.w), f2tf32(hi.w));
    }
    if (tid < 64) sAcc[tid] = 0.f;

    // ---- per-thread epilogue params (fixed h-slice per warp)
    const int r = lane >> 2, c = lane & 3;
    float ww_[2][2], bv_[2][2], bu_[2][2];
    #pragma unroll
    for (int nt = 0; nt < 2; nt++)
        #pragma unroll
        for (int jj = 0; jj < 2; jj++) {
            int h = wid * 16 + nt * 8 + c * 2 + jj;
            ww_[nt][jj] = Ww[h]; bv_[nt][jj] = bv[h]; bu_[nt][jj] = bu[h];
        }
    const float bw0 = bwp[0];
    __syncthreads();

    float esum = 0.f, wsum = 0.f;

    cp_tile(sbase + OFF_A0, bag, blockIdx.x, tid);
    asm volatile("cp.async.commit_group;" ::: "memory");

    int parity = 0;
    for (int tile = blockIdx.x; tile < NTILES; tile += GRID_SCORES) {
        asm volatile("cp.async.wait_group 0;" ::: "memory");
        __syncthreads();

        int nxt = tile + GRID_SCORES;
        if (nxt < NTILES) cp_tile(sbase + (parity ? OFF_A0 : OFF_A1), bag, nxt, tid);
        asm volatile("cp.async.commit_group;" ::: "memory");

        const char* aBase = smem + (parity ? OFF_A1 : OFF_A0);

        float accV[4][2][4], accU[4][2][4];
        #pragma unroll
        for (int mt = 0; mt < 4; mt++)
            #pragma unroll
            for (int nt = 0; nt < 2; nt++)
                #pragma unroll
                for (int q = 0; q < 4; q++) { accV[mt][nt][q] = 0.f; accU[mt][nt][q] = 0.f; }

        #pragma unroll 4
        for (int ks = 0; ks < 16; ks++) {
            uint32_t a[4][4];
            #pragma unroll
            for (int mt = 0; mt < 4; mt++) {
                const float* ap = (const float*)aBase + (mt * 16 + r) * A_ROW_F + ks * 8 + c;
                a[mt][0] = __float_as_uint(ap[0]);
                a[mt][1] = __float_as_uint(ap[8 * A_ROW_F]);
                a[mt][2] = __float_as_uint(ap[4]);
                a[mt][3] = __float_as_uint(ap[8 * A_ROW_F + 4]);
            }
            const char* bslab = smem + OFF_B + ks * 4096 + (wid * 16 + r) * 32 + c * 8;
            uint2 bV[2], bU[2];
            bV[0] = *(const uint2*)(bslab);
            bV[1] = *(const uint2*)(bslab + 256);
            bU[0] = *(const uint2*)(bslab + B_MAT_B);
            bU[1] = *(const uint2*)(bslab + B_MAT_B + 256);
            #pragma unroll
            for (int mt = 0; mt < 4; mt++) {
                mma_tf32(accV[mt][0], a[mt], bV[0]);
                mma_tf32(accV[mt][1], a[mt], bV[1]);
                mma_tf32(accU[mt][0], a[mt], bU[0]);
                mma_tf32(accU[mt][1], a[mt], bU[1]);
            }
        }

        // ---- epilogue: gate + Ww dot (thread pairs V/U fragments directly)
        #pragma unroll
        for (int mt = 0; mt < 4; mt++) {
            float slo = 0.f, shi = 0.f;
            #pragma unroll
            for (int nt = 0; nt < 2; nt++)
                #pragma unroll
                for (int jj = 0; jj < 2; jj++) {
                    float v = accV[mt][nt][jj] + bv_[nt][jj];
                    float u = accU[mt][nt][jj] + bu_[nt][jj];
                    float sg = fmaf(0.5f, tanh_fast(0.5f * u), 0.5f);
                    slo = fmaf(ww_[nt][jj] * tanh_fast(v), sg, slo);
                    v = accV[mt][nt][2 + jj] + bv_[nt][jj];
                    u = accU[mt][nt][2 + jj] + bu_[nt][jj];
                    sg = fmaf(0.5f, tanh_fast(0.5f * u), 0.5f);
                    shi = fmaf(ww_[nt][jj] * tanh_fast(v), sg, shi);
                }
            slo += __shfl_xor_sync(0xffffffffu, slo, 1);
            slo += __shfl_xor_sync(0xffffffffu, slo, 2);
            shi += __shfl_xor_sync(0xffffffffu, shi, 1);
            shi += __shfl_xor_sync(0xffffffffu, shi, 2);
            if (c == 0) {
                atomicAdd(&sAcc[mt * 16 + r], slo);
                atomicAdd(&sAcc[mt * 16 + r + 8], shi);
            }
        }
        __syncthreads();

        const int row0 = tile * TILE_R;
        if (tid < 64) {
            int grow = row0 + tid;
            float Araw = sAcc[tid] + bw0;
            sAcc[tid] = 0.f;
            float e = 0.f;
            if (grow < N_ROWS) { e = __expf(Araw); g_E[grow] = e; esum += e; }
            sE[tid] = e;
        }
        __syncthreads();

        // ---- fused weighted-bag reduction from the SMEM tile
        if (tid < 128) {
            const float* ap = (const float*)aBase + tid;
            float w = 0.f;
            #pragma unroll 8
            for (int rr = 0; rr < TILE_R; rr++) w = fmaf(sE[rr], ap[rr * A_ROW_F], w);
            wsum += w;
        }
        parity ^= 1;
    }

    // ---- final reductions
    if (tid < 128) atomicAdd(&g_wsum[tid], wsum);
    float s = esum;
    #pragma unroll
    for (int o = 16; o; o >>= 1) s += __shfl_xor_sync(0xffffffffu, s, o);
    if (lane == 0 && s != 0.f) atomicAdd(&g_sumexp, s);
}

__global__ void k_alpha(float* __restrict__ out) {
    int i = blockIdx.x * blockDim.x + threadIdx.x;
    if (i < N_ROWS) {
        float invS = __frcp_rn(g_sumexp);
        out[1 + i] = g_E[i] * invS;
    }
}

__global__ void k_head(const float* __restrict__ gf,
                       const float* __restrict__ W1, const float* __restrict__ b1,
                       const float* __restrict__ W2, const float* __restrict__ b2,
                       float* __restrict__ out) {
    __shared__ float fused[D + GDIM];
    __shared__ float hred[M];
    const int tid = threadIdx.x;
    const float invS = 1.f / g_sumexp;
    if (tid < D) fused[tid] = g_wsum[tid] * invS;
    else if (tid < D + GDIM) fused[tid] = gf[tid - D];
    __syncthreads();

    float acc = b1[tid];
    #pragma unroll 8
    for (int j = 0; j < D + GDIM; j++) acc += W1[tid * (D + GDIM) + j] * fused[j];
    float h = acc > 0.f ? acc : 0.01f * acc;
    hred[tid] = h * W2[tid];
    __syncthreads();
    for (int s = M / 2; s; s >>= 1) {
        if (tid < s) hred[tid] += hred[tid + s];
        __syncthreads();
    }
    if (tid == 0) out[0] = hred[0] + b2[0];
}

extern "C" void kernel_launch(void* const* d_in, const int* in_sizes, int n_in,
                              void* d_out, int out_size)
{
    const float* bag = (const float*)d_in[0];
    const float* gf  = (const float*)d_in[1];
    const float* Wv  = (const float*)d_in[2];
    const float* bv  = (const float*)d_in[3];
    const float* Wu  = (const float*)d_in[4];
    const float* bu  = (const float*)d_in[5];
    const float* Ww  = (const float*)d_in[6];
    const float* bw  = (const float*)d_in[7];
    const float* W1  = (const float*)d_in[8];
    const float* b1  = (const float*)d_in[9];
    const float* W2  = (const float*)d_in[10];
    const float* b2  = (const float*)d_in[11];
    float* out = (float*)d_out;

    cudaFuncSetAttribute(k_scores, cudaFuncAttributeMaxDynamicSharedMemorySize, SMEM_TOTAL);

    k_init<<<1, 256>>>();
    k_scores<<<GRID_SCORES, 256, SMEM_TOTAL>>>(bag, Wv, bv, Wu, bu, Ww, bw);
    k_alpha<<<(N_ROWS + 255) / 256, 256>>>(out);
    k_head<<<1, 256>>>(gf, W1, b1, W2, b2, out);
}